// round 11
// baseline (speedup 1.0000x reference)
#include <cuda_runtime.h>
#include <cuda_bf16.h>

// Problem dims
#define TSTEPS 499
#define BDIM 64
#define NDIM 512
#define DDIM 100
#define ODIM 10
#define KCAT 1536

// RNN kernel config
#define NCTA 128
#define NTHR 256
#define KSLICE 192          // virtual-k per warp (8 warps x 192 = 1536)
#define SUBK 16             // k per sub-chunk (1024 boundary hit at warp5 sub4: aligned)
#define NSUB 12
#define RS_SUB (SUBK * BDIM)      // 1024 floats = 4KB

// Duplicated-weight SMEM strides (in float2/u64 units); %16==4 -> broadcast-pair
// addresses land 32/64B apart in bank space (conflict-free)
#define WM1S 1540
#define WPMDS 1028
#define WS1S 516
// partials: [8 warps][64 b][13] (12 used: m1 c0..3 | pmd c0..3 | s1 c0..3)
#define PROW 13
#define PPLANE (BDIM * PROW)
// W_out smem stride for output phase (reuses partials area)
#define WOS 520

typedef unsigned long long u64;

__device__ __forceinline__ u64 fma2(u64 a, u64 b, u64 c) {
  u64 d;
  asm("fma.rn.f32x2 %0, %1, %2, %3;" : "=l"(d) : "l"(a), "l"(b), "l"(c));
  return d;
}
__device__ __forceinline__ float2 unpack2(u64 v) {
  float2 r;
  asm("mov.b64 {%0, %1}, %2;" : "=f"(r.x), "=f"(r.y) : "l"(v));
  return r;
}

// ---------------- device scratch (static; no allocations) ----------------
__device__ float g_U[2][TSTEPS][BDIM][NDIM];   // [0]=pmd drive, [1]=s1 drive (bias folded)
__device__ float g_r[2][KCAT][BDIM];           // ping-pong rcat, k-major [k][b]
__device__ float g_rm1h[TSTEPS][BDIM][NDIM];   // r_m1 history for deferred output GEMM
__device__ unsigned g_gen;
__device__ unsigned g_count;

// ---------------- setup: init fold + time-parallel input projections ----------------
__global__ void setup_kernel(const float* __restrict__ X,
                             const float* __restrict__ W_in_pmd,
                             const float* __restrict__ W_in_s1,
                             const float* __restrict__ b_pmd,
                             const float* __restrict__ b_s1) {
  __shared__ __align__(16) float Xs[32][DDIM];
  __shared__ __align__(16) float Ws[64][DDIM];
  const int tIdx = blockIdx.x;
  const int y    = blockIdx.y;
  const int tid  = threadIdx.x;

  // folded init (rnn_kernel launches after this kernel completes)
  if (y == 0) {
    if (tIdx == 0 && tid == 0) { g_gen = 0u; g_count = 0u; }
    if (tIdx < 96) {
      float* r0 = &g_r[0][0][0];  // 98304 floats / 96 blocks = 1024 each
      int base = tIdx * 1024;
#pragma unroll
      for (int j = 0; j < 4; j++) r0[base + tid + j * NTHR] = 0.0f;
    }
  }

  const int reg   = y >> 4;
  const int bhalf = (y >> 3) & 1;
  const int nblk  = y & 7;
  const int b0 = bhalf * 32;
  const int n0 = nblk * 64;
  const float* W    = reg ? W_in_s1 : W_in_pmd;
  const float* bias = reg ? b_s1    : b_pmd;
  const float* Xt = X + (size_t)(tIdx + 1) * (BDIM * DDIM);

  for (int i = tid; i < 32 * DDIM; i += NTHR)
    Xs[i / DDIM][i % DDIM] = Xt[(b0 + i / DDIM) * DDIM + (i % DDIM)];
  for (int i = tid; i < 64 * DDIM; i += NTHR)
    Ws[i / DDIM][i % DDIM] = W[(n0 + i / DDIM) * DDIM + (i % DDIM)];
  __syncthreads();

  const int ty = tid >> 4, tx = tid & 15;
  const int bb = 2 * ty, nn = 4 * tx;
  float acc[2][4];
#pragma unroll
  for (int j = 0; j < 4; j++) {
    float bv = bias[n0 + nn + j];
    acc[0][j] = bv; acc[1][j] = bv;
  }
#pragma unroll
  for (int k = 0; k < DDIM; k += 4) {
    float4 x0 = *(const float4*)&Xs[bb][k];
    float4 x1 = *(const float4*)&Xs[bb + 1][k];
#pragma unroll
    for (int j = 0; j < 4; j++) {
      float4 wv = *(const float4*)&Ws[nn + j][k];
      acc[0][j] += x0.x * wv.x + x0.y * wv.y + x0.z * wv.z + x0.w * wv.w;
      acc[1][j] += x1.x * wv.x + x1.y * wv.y + x1.z * wv.z + x1.w * wv.w;
    }
  }
#pragma unroll
  for (int i2 = 0; i2 < 2; i2++)
#pragma unroll
    for (int j = 0; j < 4; j++)
      g_U[reg][tIdx][b0 + bb + i2][n0 + nn + j] = acc[i2][j];
}

// ---------------- persistent serial RNN core (+ fused output projection) ----------------
__device__ __forceinline__ void cp_sub(float* dst, const float* src, int lane) {
  // contiguous 4KB (16 k-rows x 64 b), 8 float4 per lane
#pragma unroll
  for (int j = 0; j < 8; j++) {
    int o = (lane + j * 32) * 4;
    unsigned s = (unsigned)__cvta_generic_to_shared(dst + o);
    asm volatile("cp.async.cg.shared.global [%0], [%1], 16;\n" :: "r"(s), "l"(src + o) : "memory");
  }
}

// rlo/rhi pack b-pairs {b0,b1},{b2,b3}; weight u64s are pre-duplicated {w,w}
#define FMA2K(RLO, RHI, WA, WB, VA, VB, AO)                                 \
  am2[0][0] = fma2(RLO, WA, am2[0][0]); am2[1][0] = fma2(RHI, WA, am2[1][0]); \
  am2[0][1] = fma2(RLO, WB, am2[0][1]); am2[1][1] = fma2(RHI, WB, am2[1][1]); \
  AO[0][0]  = fma2(RLO, VA, AO[0][0]);  AO[1][0]  = fma2(RHI, VA, AO[1][0]);  \
  AO[0][1]  = fma2(RLO, VB, AO[0][1]);  AO[1][1]  = fma2(RHI, VB, AO[1][1]);

#define INNER2(AO, V1, V2)                                                  \
  _Pragma("unroll")                                                         \
  for (int kk = 0; kk < SUBK; kk += 4) {                                    \
    ulonglong2 r0 = *(const ulonglong2*)(rsc + (kk + 0) * BDIM + bg4);      \
    ulonglong2 r1 = *(const ulonglong2*)(rsc + (kk + 1) * BDIM + bg4);      \
    ulonglong2 r2 = *(const ulonglong2*)(rsc + (kk + 2) * BDIM + bg4);      \
    ulonglong2 r3 = *(const ulonglong2*)(rsc + (kk + 3) * BDIM + bg4);      \
    ulonglong2 wa01 = *(const ulonglong2*)(w1a + kk);                       \
    ulonglong2 wa23 = *(const ulonglong2*)(w1a + kk + 2);                   \
    ulonglong2 wb01 = *(const ulonglong2*)(w1b + kk);                       \
    ulonglong2 wb23 = *(const ulonglong2*)(w1b + kk + 2);                   \
    ulonglong2 va01 = *(const ulonglong2*)((V1) + kk);                      \
    ulonglong2 va23 = *(const ulonglong2*)((V1) + kk + 2);                  \
    ulonglong2 vb01 = *(const ulonglong2*)((V2) + kk);                      \
    ulonglong2 vb23 = *(const ulonglong2*)((V2) + kk + 2);                  \
    FMA2K(r0.x, r0.y, wa01.x, wb01.x, va01.x, vb01.x, AO)                   \
    FMA2K(r1.x, r1.y, wa01.y, wb01.y, va01.y, vb01.y, AO)                   \
    FMA2K(r2.x, r2.y, wa23.x, wb23.x, va23.x, vb23.x, AO)                   \
    FMA2K(r3.x, r3.y, wa23.y, wb23.y, va23.y, vb23.y, AO)                   \
  }

extern __shared__ float s_mem[];

__global__ void __launch_bounds__(NTHR, 1)
rnn_kernel(const float* __restrict__ W_rec_m1,
           const float* __restrict__ W_rec_pmd,
           const float* __restrict__ W_rec_s1,
           const float* __restrict__ b_m1,
           const float* __restrict__ W_pmd_m1,
           const float* __restrict__ W_s1_m1,
           const float* __restrict__ W_m1_pmd,
           const float* __restrict__ W_out,
           float* __restrict__ out) {
  u64* wm1_64  = (u64*)s_mem;                 // [4][WM1S]  vk: rec_m1 | pmd_m1 | s1_m1 (dup'd)
  u64* wpmd_64 = wm1_64 + 4 * WM1S;           // [4][WPMDS] vk: m1_pmd | rec_pmd (dup'd)
  u64* ws1_64  = wpmd_64 + 4 * WPMDS;         // [4][WS1S]  vk: rec_s1 (dup'd)
  float* rs   = (float*)(ws1_64 + 4 * WS1S);  // [8 warps][2][SUBK][BDIM]
  float* part = rs + 8 * 2 * RS_SUB;          // [8][BDIM][PROW]

  const int cta = blockIdx.x;
  const int tid = threadIdx.x;
  const int nbase = cta * 4;

  // cache this CTA's weight column slices in SMEM, duplicated {w,w}, for the whole run
  {
    float2* m1v = (float2*)wm1_64;
    float2* pv  = (float2*)wpmd_64;
    float2* sv  = (float2*)ws1_64;
    for (int i = tid; i < 4 * NDIM; i += NTHR) {
      int slot = i >> 9;
      int k = i & 511;
      int n = nbase + slot;
      float w;
      w = W_rec_m1[n * NDIM + k];  m1v[slot * WM1S + k]        = make_float2(w, w);
      w = W_pmd_m1[n * NDIM + k];  m1v[slot * WM1S + 512 + k]  = make_float2(w, w);
      w = W_s1_m1[n * NDIM + k];   m1v[slot * WM1S + 1024 + k] = make_float2(w, w);
      w = W_m1_pmd[n * NDIM + k];  pv[slot * WPMDS + k]        = make_float2(w, w);
      w = W_rec_pmd[n * NDIM + k]; pv[slot * WPMDS + 512 + k]  = make_float2(w, w);
      w = W_rec_s1[n * NDIM + k];  sv[slot * WS1S + k]         = make_float2(w, w);
    }
  }

  // compute-role mapping: warp owns 192 virtual-k; halves own col pairs; bg owns 4 b-rows
  const int warp = tid >> 5;
  const int lane = tid & 31;
  const int cg = (tid >> 4) & 1;
  const int bg4 = (tid & 15) * 4;
  const int kbase = warp * KSLICE;
  const int ca = cg * 2, cb = cg * 2 + 1;
  float* rs0 = rs + warp * 2 * RS_SUB;

  // state-role mapping: thread owns cell (b, col)
  const int b = tid >> 2;
  const int slot = tid & 3;
  const int col = nbase + slot;
  const float bias_m1 = b_m1[col];
  const float a = 0.1f;
  const float oma = 1.0f - a;
  float x_m1 = 0.0f, x_pmd = 0.0f, x_s1 = 0.0f;
  __syncthreads();

  for (int t = 1; t <= TSTEPS; t++) {
    const float u_pmd = __ldg(&g_U[0][t - 1][b][col]);
    const float u_s1  = __ldg(&g_U[1][t - 1][b][col]);

    const float* rprev = &g_r[(t - 1) & 1][0][0];   // [k][b]

    // prime first two sub-chunks (warp-local double buffer; no CTA syncs in mainloop)
    cp_sub(rs0, rprev + (size_t)kbase * BDIM, lane);
    asm volatile("cp.async.commit_group;\n" ::: "memory");
    cp_sub(rs0 + RS_SUB, rprev + (size_t)(kbase + SUBK) * BDIM, lane);
    asm volatile("cp.async.commit_group;\n" ::: "memory");

    u64 am2[2][2] = {{0ull, 0ull}, {0ull, 0ull}};   // m1: b-pairs x cols
    u64 ap2[2][2] = {{0ull, 0ull}, {0ull, 0ull}};   // pmd
    u64 as2[2][2] = {{0ull, 0ull}, {0ull, 0ull}};   // s1

#pragma unroll 1
    for (int s = 0; s < NSUB; s++) {
      if (s < NSUB - 1) { asm volatile("cp.async.wait_group 1;\n" ::: "memory"); }
      else              { asm volatile("cp.async.wait_group 0;\n" ::: "memory"); }

      const int k0 = kbase + s * SUBK;
      const float* rsc = rs0 + (s & 1) * RS_SUB;
      const u64* w1a = wm1_64 + (size_t)ca * WM1S + k0;
      const u64* w1b = wm1_64 + (size_t)cb * WM1S + k0;
      if (k0 < 1024) {   // sub-chunks never straddle the 1024 boundary
        const u64* v1 = wpmd_64 + (size_t)ca * WPMDS + k0;
        const u64* v2 = wpmd_64 + (size_t)cb * WPMDS + k0;
        INNER2(ap2, v1, v2)
      } else {
        const u64* v1 = ws1_64 + (size_t)ca * WS1S + (k0 - 1024);
        const u64* v2 = ws1_64 + (size_t)cb * WS1S + (k0 - 1024);
        INNER2(as2, v1, v2)
      }
      if (s + 2 < NSUB) {
        cp_sub(rs0 + (s & 1) * RS_SUB, rprev + (size_t)(k0 + 2 * SUBK) * BDIM, lane);
        asm volatile("cp.async.commit_group;\n" ::: "memory");
      }
    }

    // write k-slice partials (unpack b-pairs back to rows)
    {
      float* p0 = part + warp * PPLANE + bg4 * PROW;
      float2 v;
      v = unpack2(am2[0][0]); p0[0 * PROW + ca] = v.x; p0[1 * PROW + ca] = v.y;
      v = unpack2(am2[1][0]); p0[2 * PROW + ca] = v.x; p0[3 * PROW + ca] = v.y;
      v = unpack2(am2[0][1]); p0[0 * PROW + cb] = v.x; p0[1 * PROW + cb] = v.y;
      v = unpack2(am2[1][1]); p0[2 * PROW + cb] = v.x; p0[3 * PROW + cb] = v.y;
      v = unpack2(ap2[0][0]); p0[0 * PROW + 4 + ca] = v.x; p0[1 * PROW + 4 + ca] = v.y;
      v = unpack2(ap2[1][0]); p0[2 * PROW + 4 + ca] = v.x; p0[3 * PROW + 4 + ca] = v.y;
      v = unpack2(ap2[0][1]); p0[0 * PROW + 4 + cb] = v.x; p0[1 * PROW + 4 + cb] = v.y;
      v = unpack2(ap2[1][1]); p0[2 * PROW + 4 + cb] = v.x; p0[3 * PROW + 4 + cb] = v.y;
      v = unpack2(as2[0][0]); p0[0 * PROW + 8 + ca] = v.x; p0[1 * PROW + 8 + ca] = v.y;
      v = unpack2(as2[1][0]); p0[2 * PROW + 8 + ca] = v.x; p0[3 * PROW + 8 + ca] = v.y;
      v = unpack2(as2[0][1]); p0[0 * PROW + 8 + cb] = v.x; p0[1 * PROW + 8 + cb] = v.y;
      v = unpack2(as2[1][1]); p0[2 * PROW + 8 + cb] = v.x; p0[3 * PROW + 8 + cb] = v.y;
    }
    __syncthreads();

    // reduce over 8 k-slices + leaky update + tanh (state role)
    float sm = 0.f, sp = 0.f, ss = 0.f;
#pragma unroll
    for (int q = 0; q < 8; q++) {
      const float* p = part + q * PPLANE + b * PROW;
      sm += p[slot]; sp += p[4 + slot]; ss += p[8 + slot];
    }
    x_m1  = oma * x_m1  + a * (sm + bias_m1);
    x_pmd = oma * x_pmd + a * (sp + u_pmd);
    x_s1  = oma * x_s1  + a * (ss + u_s1);
    const float r_m1  = tanhf(x_m1);
    const float r_pmd = tanhf(x_pmd);
    const float r_s1v = tanhf(x_s1);

    float* rn = &g_r[t & 1][0][0];
    rn[col * BDIM + b]          = r_m1;
    rn[(512 + col) * BDIM + b]  = r_pmd;
    rn[(1024 + col) * BDIM + b] = r_s1v;
    g_rm1h[t - 1][b][col] = r_m1;

    // ---- grid barrier (monotone generation; all 128 CTAs resident) ----
    __threadfence();
    __syncthreads();
    if (tid == 0) {
      unsigned prev = atomicAdd(&g_count, 1u);
      if (prev == (unsigned)NCTA * (unsigned)t - 1u) {
        __threadfence();
        *((volatile unsigned*)&g_gen) = (unsigned)t;
      } else {
        while (*((volatile unsigned*)&g_gen) < (unsigned)t) { }
        __threadfence();
      }
    }
    __syncthreads();
  }

  // ---------------- fused output projection: out[t] = r_m1[t] @ W_out^T ----------------
  float* wo = part;   // reuse partials area: ODIM*WOS = 5200 <= 6656 floats
  for (int i = tid; i < ODIM * NDIM; i += NTHR)
    wo[(i / NDIM) * WOS + (i % NDIM)] = W_out[i];
  __syncthreads();

  for (int t = cta; t < TSTEPS; t += NCTA) {
    const float* R = &g_rm1h[t][0][0];
    for (int idx = tid; idx < BDIM * ODIM; idx += NTHR) {
      int bb = idx / ODIM, o = idx % ODIM;
      const float* r = R + bb * NDIM;
      const float* w = wo + o * WOS;
      float s0 = 0.f, s1 = 0.f, s2 = 0.f, s3 = 0.f;
#pragma unroll 8
      for (int k = 0; k < NDIM; k += 16) {
        float4 r0 = *(const float4*)(r + k);
        float4 r1 = *(const float4*)(r + k + 4);
        float4 r2 = *(const float4*)(r + k + 8);
        float4 r3 = *(const float4*)(r + k + 12);
        float4 w0 = *(const float4*)(w + k);
        float4 w1 = *(const float4*)(w + k + 4);
        float4 w2 = *(const float4*)(w + k + 8);
        float4 w3 = *(const float4*)(w + k + 12);
        s0 += r0.x * w0.x + r0.y * w0.y + r0.z * w0.z + r0.w * w0.w;
        s1 += r1.x * w1.x + r1.y * w1.y + r1.z * w1.z + r1.w * w1.w;
        s2 += r2.x * w2.x + r2.y * w2.y + r2.z * w2.z + r2.w * w2.w;
        s3 += r3.x * w3.x + r3.y * w3.y + r3.z * w3.z + r3.w * w3.w;
      }
      out[t * (BDIM * ODIM) + idx] = (s0 + s1) + (s2 + s3);
    }
  }
}

// ---------------- launch ----------------
extern "C" void kernel_launch(void* const* d_in, const int* in_sizes, int n_in,
                              void* d_out, int out_size) {
  (void)in_sizes; (void)n_in; (void)out_size;
  const float* X         = (const float*)d_in[0];
  const float* W_rec_m1  = (const float*)d_in[1];
  const float* W_rec_pmd = (const float*)d_in[2];
  const float* W_rec_s1  = (const float*)d_in[3];
  const float* b_m1      = (const float*)d_in[4];
  const float* b_pmd     = (const float*)d_in[5];
  const float* b_s1      = (const float*)d_in[6];
  const float* W_pmd_m1  = (const float*)d_in[7];
  const float* W_s1_m1   = (const float*)d_in[8];
  const float* W_m1_pmd  = (const float*)d_in[9];
  const float* W_in_pmd  = (const float*)d_in[10];
  const float* W_in_s1   = (const float*)d_in[11];
  const float* W_out     = (const float*)d_in[12];
  float* out = (float*)d_out;

  dim3 gA(TSTEPS, 32);
  setup_kernel<<<gA, NTHR>>>(X, W_in_pmd, W_in_s1, b_pmd, b_s1);

  const int smem_bytes =
      (4 * (WM1S + WPMDS + WS1S) * 2 + 8 * 2 * RS_SUB + 8 * PPLANE) * (int)sizeof(float);
  cudaFuncSetAttribute(rnn_kernel, cudaFuncAttributeMaxDynamicSharedMemorySize, smem_bytes);
  rnn_kernel<<<NCTA, NTHR, smem_bytes>>>(W_rec_m1, W_rec_pmd, W_rec_s1, b_m1,
                                         W_pmd_m1, W_s1_m1, W_m1_pmd, W_out, out);
}